// round 15
// baseline (speedup 1.0000x reference)
#include <cuda_runtime.h>
#include <cuda_fp16.h>
#include <math.h>
#include <stdint.h>

// Problem constants
#define T_TOK 2048        // B*S
#define D_DIM 1024
#define H_DIM 4096
#define E_NUM 8
#define TOPK 2
#define N_SLOTS (T_TOK * TOPK)    // 4096
#define OUT_ELEMS (T_TOK * D_DIM) // 2097152

// ---------------- device scratch (static, allocation-free) ----------------
__device__ int   g_offsets[E_NUM + 1];
__device__ int   g_cursor[E_NUM];
__device__ int   g_slot_tok[N_SLOTS];
__device__ float g_slot_prob[N_SLOTS];
__device__ int   g_tok_slot[T_TOK * TOPK];
__device__ int   g_top_e[T_TOK * TOPK];
__device__ float g_top_p[T_TOK * TOPK];
__device__ float g_probs8[T_TOK * E_NUM];

__device__ __align__(16) __half g_xh[(size_t)T_TOK * D_DIM];
__device__ __align__(16) __half g_W1h[(size_t)E_NUM * H_DIM * D_DIM];
__device__ __align__(16) __half g_W2h[(size_t)E_NUM * D_DIM * H_DIM];
__device__ __align__(16) __half g_Hh[(size_t)N_SLOTS * H_DIM];
__device__ __align__(16) float g_Y[(size_t)N_SLOTS * D_DIM];

// ---------------- PTX helpers (sm_80-class only; no 'a' features) ----------------
__device__ __forceinline__ uint32_t smem_u32(const void* p) {
    return (uint32_t)__cvta_generic_to_shared(p);
}

__device__ __forceinline__ void cp16(uint32_t saddr, const void* gaddr) {
    asm volatile("cp.async.cg.shared.global [%0], [%1], 16;" :: "r"(saddr), "l"(gaddr));
}
#define CP_COMMIT() asm volatile("cp.async.commit_group;" ::: "memory")
#define CP_WAIT_2() asm volatile("cp.async.wait_group 2;" ::: "memory")

__device__ __forceinline__ void ldsm_x4(uint32_t* r, uint32_t addr) {
    asm volatile("ldmatrix.sync.aligned.m8n8.x4.shared.b16 {%0,%1,%2,%3}, [%4];"
        : "=r"(r[0]), "=r"(r[1]), "=r"(r[2]), "=r"(r[3]) : "r"(addr));
}
__device__ __forceinline__ void ldsm_x2(uint32_t* r, uint32_t addr) {
    asm volatile("ldmatrix.sync.aligned.m8n8.x2.shared.b16 {%0,%1}, [%2];"
        : "=r"(r[0]), "=r"(r[1]) : "r"(addr));
}

__device__ __forceinline__ void mma16816(float* d, const uint32_t* a, const uint32_t* b) {
    asm volatile(
        "mma.sync.aligned.m16n8k16.row.col.f32.f16.f16.f32 "
        "{%0,%1,%2,%3}, {%4,%5,%6,%7}, {%8,%9}, {%0,%1,%2,%3};"
        : "+f"(d[0]), "+f"(d[1]), "+f"(d[2]), "+f"(d[3])
        : "r"(a[0]), "r"(a[1]), "r"(a[2]), "r"(a[3]), "r"(b[0]), "r"(b[1]));
}

// ---------------- router ----------------
__global__ void router_kernel(const float* __restrict__ x,
                              const float* __restrict__ Wg) {
    const int t = blockIdx.x;
    const float* xr = x + (size_t)t * D_DIM;
    float acc[E_NUM];
#pragma unroll
    for (int e = 0; e < E_NUM; e++) acc[e] = 0.f;

    for (int d = threadIdx.x; d < D_DIM; d += 128) {
        float xv = xr[d];
#pragma unroll
        for (int e = 0; e < E_NUM; e++)
            acc[e] = fmaf(xv, Wg[e * D_DIM + d], acc[e]);
    }
#pragma unroll
    for (int e = 0; e < E_NUM; e++)
#pragma unroll
        for (int off = 16; off > 0; off >>= 1)
            acc[e] += __shfl_xor_sync(0xffffffffu, acc[e], off);

    __shared__ float s[E_NUM][4];
    const int warp = threadIdx.x >> 5, lane = threadIdx.x & 31;
    if (lane == 0)
#pragma unroll
        for (int e = 0; e < E_NUM; e++) s[e][warp] = acc[e];
    __syncthreads();

    if (threadIdx.x == 0) {
        float lg[E_NUM];
#pragma unroll
        for (int e = 0; e < E_NUM; e++)
            lg[e] = s[e][0] + s[e][1] + s[e][2] + s[e][3];
        float mx = lg[0];
#pragma unroll
        for (int e = 1; e < E_NUM; e++) mx = fmaxf(mx, lg[e]);
        float se = 0.f, pe[E_NUM];
#pragma unroll
        for (int e = 0; e < E_NUM; e++) { pe[e] = expf(lg[e] - mx); se += pe[e]; }
        float inv = 1.f / se;
#pragma unroll
        for (int e = 0; e < E_NUM; e++) g_probs8[t * E_NUM + e] = pe[e] * inv;
        int i1 = 0;
#pragma unroll
        for (int e = 1; e < E_NUM; e++) if (lg[e] > lg[i1]) i1 = e;
        int i2 = -1;
#pragma unroll
        for (int e = 0; e < E_NUM; e++) {
            if (e == i1) continue;
            if (i2 < 0 || lg[e] > lg[i2]) i2 = e;
        }
        float v1 = lg[i1], v2 = lg[i2];
        float m = fmaxf(v1, v2);
        float e1 = expf(v1 - m), e2 = expf(v2 - m);
        float denom = 1.f / (e1 + e2);
        g_top_e[t * 2 + 0] = i1;  g_top_e[t * 2 + 1] = i2;
        g_top_p[t * 2 + 0] = e1 * denom;
        g_top_p[t * 2 + 1] = e2 * denom;
    }
}

// ---------------- finalize: counts + offsets + scatter + aux (one CTA) ------
__global__ void finalize_kernel(float* __restrict__ out, int out_size) {
    const int tid = threadIdx.x;   // 1024 threads
    __shared__ int s_counts[E_NUM];
    if (tid < E_NUM) s_counts[tid] = 0;
    __syncthreads();

    // counts from g_top_e (order-independent sum -> deterministic)
    for (int i = tid; i < T_TOK * TOPK; i += 1024)
        atomicAdd(&s_counts[g_top_e[i]], 1);
    __syncthreads();

    if (tid == 0) {
        int o = 0;
        for (int e = 0; e < E_NUM; e++) {
            g_offsets[e] = o; g_cursor[e] = o; o += s_counts[e];
        }
        g_offsets[E_NUM] = o;
    }
    __syncthreads();

    // scatter
    for (int t = tid; t < T_TOK; t += 1024) {
#pragma unroll
        for (int k = 0; k < TOPK; k++) {
            int e = g_top_e[t * 2 + k];
            int sidx = atomicAdd(&g_cursor[e], 1);
            g_slot_tok[sidx]  = t;
            g_slot_prob[sidx] = g_top_p[t * 2 + k];
            g_tok_slot[t * 2 + k] = sidx;
        }
    }

    // aux loss (deterministic reduction)
    __shared__ float red[E_NUM][1024];
    float ls[E_NUM];
#pragma unroll
    for (int e = 0; e < E_NUM; e++) ls[e] = 0.f;
    for (int t = tid; t < T_TOK; t += 1024)
#pragma unroll
        for (int e = 0; e < E_NUM; e++) ls[e] += g_probs8[t * E_NUM + e];
#pragma unroll
    for (int e = 0; e < E_NUM; e++) red[e][tid] = ls[e];
    __syncthreads();
    for (int st = 512; st > 0; st >>= 1) {
        if (tid < st)
#pragma unroll
            for (int e = 0; e < E_NUM; e++)
                red[e][tid] += red[e][tid + st];
        __syncthreads();
    }
    if (tid == 0 && out_size > OUT_ELEMS) {
        float aux = 0.f;
        for (int e = 0; e < E_NUM; e++)
            aux += (red[e][0] / (float)T_TOK) * ((float)s_counts[e] / (float)T_TOK);
        out[OUT_ELEMS] = (float)E_NUM * aux;
    }
}

// ---------------- fp32 -> fp16 round (x, wide stores) ----------------
__global__ void round_kernel(const float4* __restrict__ src,
                             uint4* __restrict__ dst, int n8) {
    int i = blockIdx.x * blockDim.x + threadIdx.x;
    int stride = gridDim.x * blockDim.x;
    for (; i < n8; i += stride) {
        float4 v0 = src[2 * i];
        float4 v1 = src[2 * i + 1];
        uint4 o;
        o.x = (uint32_t)__half_as_ushort(__float2half_rn(v0.x)) |
              ((uint32_t)__half_as_ushort(__float2half_rn(v0.y)) << 16);
        o.y = (uint32_t)__half_as_ushort(__float2half_rn(v0.z)) |
              ((uint32_t)__half_as_ushort(__float2half_rn(v0.w)) << 16);
        o.z = (uint32_t)__half_as_ushort(__float2half_rn(v1.x)) |
              ((uint32_t)__half_as_ushort(__float2half_rn(v1.y)) << 16);
        o.w = (uint32_t)__half_as_ushort(__float2half_rn(v1.z)) |
              ((uint32_t)__half_as_ushort(__float2half_rn(v1.w)) << 16);
        dst[i] = o;
    }
}

// ---------------- fp32 -> fp16 round, both weight tensors in one launch -----
#define W1_N8 ((int)((size_t)E_NUM * H_DIM * D_DIM / 8))
#define W2_N8 ((int)((size_t)E_NUM * D_DIM * H_DIM / 8))
__global__ void round_w_kernel(const float4* __restrict__ w1,
                               const float4* __restrict__ w2,
                               uint4* __restrict__ d1, uint4* __restrict__ d2) {
    int i = blockIdx.x * blockDim.x + threadIdx.x;
    int stride = gridDim.x * blockDim.x;
    for (; i < W1_N8 + W2_N8; i += stride) {
        const float4* src = (i < W1_N8) ? w1 : w2;
        uint4* dst = (i < W1_N8) ? d1 : d2;
        int j = (i < W1_N8) ? i : (i - W1_N8);
        float4 v0 = src[2 * j];
        float4 v1 = src[2 * j + 1];
        uint4 o;
        o.x = (uint32_t)__half_as_ushort(__float2half_rn(v0.x)) |
              ((uint32_t)__half_as_ushort(__float2half_rn(v0.y)) << 16);
        o.y = (uint32_t)__half_as_ushort(__float2half_rn(v0.z)) |
              ((uint32_t)__half_as_ushort(__float2half_rn(v0.w)) << 16);
        o.z = (uint32_t)__half_as_ushort(__float2half_rn(v1.x)) |
              ((uint32_t)__half_as_ushort(__float2half_rn(v1.y)) << 16);
        o.w = (uint32_t)__half_as_ushort(__float2half_rn(v1.z)) |
              ((uint32_t)__half_as_ushort(__float2half_rn(v1.w)) << 16);
        dst[j] = o;
    }
}

// ---------------- mma.sync grouped expert GEMM (256 threads, fp16) ----------
// EXACT round-12 configuration (best measured): block tile 128x128, 8 warps
// in 2x4 grid, warp tile 64x32, __launch_bounds__(256, 2) -> 2 CTAs/SM,
// K=32 per stage, 4 smem stages (80 KB), prefetch depth 3, one sync/chunk.

#define KCHUNK 32
#define ROWPAD 40
#define ROWB   (ROWPAD * 2)            // 80 bytes per smem row
#define NSTAGE 4
#define BM 128
#define BN 128

template <int N_DIM, int K_DIM, bool FC1>
__global__ void __launch_bounds__(256, 2)
expert_gemm_mma3(const __half* __restrict__ A_g,
                 const __half* __restrict__ B_g,
                 const float* __restrict__ bias,
                 __half* __restrict__ H_out,
                 float* __restrict__ Y_out) {
    constexpr int NC = K_DIM / KCHUNK;
    constexpr int OFF_A = 0;
    constexpr int OFF_B = BM * ROWB;
    constexpr int ROWS_TOT = BM + BN;       // 256
    constexpr int STAGE_B = ROWS_TOT * ROWB;
    constexpr int NJ = 4;                   // 1024 chunks / 256 threads

    const int e = blockIdx.z;
    const int row_beg = g_offsets[e];
    const int row_end = g_offsets[e + 1];
    const int m0 = row_beg + blockIdx.y * BM;
    if (m0 >= row_end) return;
    const int n0 = blockIdx.x * BN;

    const __half* B_e = B_g + (size_t)e * N_DIM * K_DIM;
    const float* biasE = bias + e * N_DIM;

    extern __shared__ char smem[];
    const uint32_t smb = smem_u32(smem);
    const int tid = threadIdx.x;
    const int wid = tid >> 5;
    const int lane = tid & 31;
    const int warp_m = wid >> 2;   // 0..1  (64-row slice)
    const int warp_n = wid & 3;    // 0..3  (32-col slice)

    // ---- per-thread cp.async sources: 4 chunks (chunk id = tid + 256j) ----
    const __half* gsrc[NJ];
    uint32_t sOff[NJ];
#pragma unroll
    for (int j = 0; j < NJ; j++) {
        const int cidx = tid + 256 * j;     // 0..1023
        const int r = cidx >> 2;            // 0..255
        const int c16 = cidx & 3;
        const int kc8 = c16 * 8;
        if (r < BM) {
            int rowg = m0 + r;
            int clr = rowg < row_end ? rowg : (row_end - 1);
            int atok = FC1 ? g_slot_tok[clr] : clr;
            gsrc[j] = A_g + (size_t)atok * K_DIM + kc8;
            sOff[j] = (uint32_t)(OFF_A + r * ROWB + c16 * 16);
        } else {
            int rb = r - BM;
            gsrc[j] = B_e + (size_t)(n0 + rb) * K_DIM + kc8;
            sOff[j] = (uint32_t)(OFF_B + rb * ROWB + c16 * 16);
        }
    }

    // ---- ldmatrix per-thread base byte offsets ----
    const int l15 = lane & 15;
    const uint32_t aFrag = (uint32_t)(OFF_A + (warp_m * 64 + l15) * ROWB + (lane >> 4) * 16);
    const uint32_t bFrag = (uint32_t)(OFF_B + (warp_n * 32 + (l15 & 7)) * ROWB + ((l15 >> 3) & 1) * 16);

    float d[4][4][4];
#pragma unroll
    for (int mi = 0; mi < 4; mi++)
#pragma unroll
        for (int ni = 0; ni < 4; ni++)
#pragma unroll
            for (int q = 0; q < 4; q++) d[mi][ni][q] = 0.f;

#define ISSUE_STAGE(cidx2)                                                         \
    do {                                                                           \
        const uint32_t sb = smb + ((cidx2) % NSTAGE) * STAGE_B;                    \
        const int kk = (cidx2) * KCHUNK;                                           \
        _Pragma("unroll")                                                          \
        for (int j = 0; j < NJ; j++)                                               \
            cp16(sb + sOff[j], gsrc[j] + kk);                                      \
    } while (0)

    // prologue: 3 stages in flight
    ISSUE_STAGE(0); CP_COMMIT();
    ISSUE_STAGE(1); CP_COMMIT();
    ISSUE_STAGE(2); CP_COMMIT();

    for (int c = 0; c < NC; ++c) {
        CP_WAIT_2();       // stage c resident (uniform: one commit per iteration)
        __syncthreads();   // also guards reuse of buffer (c+3)%4 (read last iter)

        if (c + 3 < NC) ISSUE_STAGE(c + 3);
        CP_COMMIT();

        const uint32_t sb = smb + (c % NSTAGE) * STAGE_B;
        const uint32_t aB = sb + aFrag;
        const uint32_t bB = sb + bFrag;

#pragma unroll
        for (int ks = 0; ks < 2; ks++) {
            uint32_t Af[4][4], Bf[4][2];
#pragma unroll
            for (int mi = 0; mi < 4; mi++)
                ldsm_x4(Af[mi], aB + mi * (16 * ROWB) + ks * 32);
#pragma unroll
            for (int ni = 0; ni < 4; ni++)
                ldsm_x2(Bf[ni], bB + ni * (8 * ROWB) + ks * 32);
#pragma unroll
            for (int mi = 0; mi < 4; mi++)
#pragma unroll
                for (int ni = 0; ni < 4; ni++)
                    mma16816(d[mi][ni], Af[mi], Bf[ni]);
        }
    }

    // ---- epilogue ----
    const int rl = lane >> 2;          // 0..7
    const int cl = (lane & 3) * 2;     // 0,2,4,6
#pragma unroll
    for (int mi = 0; mi < 4; mi++) {
#pragma unroll
        for (int half = 0; half < 2; half++) {
            const int row = m0 + warp_m * 64 + mi * 16 + rl + half * 8;
            if (row >= row_end) continue;
            if (FC1) {
#pragma unroll
                for (int ni = 0; ni < 4; ni++) {
                    const int col = n0 + warp_n * 32 + ni * 8 + cl;
                    float v0 = fmaxf(d[mi][ni][half * 2 + 0] + biasE[col], 0.f);
                    float v1 = fmaxf(d[mi][ni][half * 2 + 1] + biasE[col + 1], 0.f);
                    __half h0 = __float2half_rn(v0), h1 = __float2half_rn(v1);
                    uint32_t hp = (uint32_t)__half_as_ushort(h0) |
                                  ((uint32_t)__half_as_ushort(h1) << 16);
                    *(uint32_t*)(H_out + (size_t)row * N_DIM + col) = hp;
                }
            } else {
                const float p = g_slot_prob[row];
#pragma unroll
                for (int ni = 0; ni < 4; ni++) {
                    const int col = n0 + warp_n * 32 + ni * 8 + cl;
                    float2 ov;
                    ov.x = (d[mi][ni][half * 2 + 0] + biasE[col])     * p;
                    ov.y = (d[mi][ni][half * 2 + 1] + biasE[col + 1]) * p;
                    *(float2*)(Y_out + (size_t)row * N_DIM + col) = ov;
                }
            }
        }
    }
#undef ISSUE_STAGE
}

#define SMEM_GEMM (NSTAGE * (BM + BN) * ROWB)   // 81920

// ---------------- combine ----------------
__global__ void combine_kernel(float* __restrict__ out) {
    const int t = blockIdx.x;
    const int s0 = g_tok_slot[t * 2 + 0];
    const int s1 = g_tok_slot[t * 2 + 1];
    const float4* y0 = (const float4*)(g_Y + (size_t)s0 * D_DIM);
    const float4* y1 = (const float4*)(g_Y + (size_t)s1 * D_DIM);
    float4* o = (float4*)(out + (size_t)t * D_DIM);
    int i = threadIdx.x;
    float4 a = y0[i], b = y1[i];
    o[i] = make_float4(a.x + b.x, a.y + b.y, a.z + b.z, a.w + b.w);
}

// ---------------- launch ----------------
extern "C" void kernel_launch(void* const* d_in, const int* in_sizes, int n_in,
                              void* d_out, int out_size) {
    const float* x  = (const float*)d_in[0];   // [2,1024,1024]
    const float* Wg = (const float*)d_in[1];   // [8,1024]
    const float* W1 = (const float*)d_in[2];   // [8,4096,1024]
    const float* b1 = (const float*)d_in[3];   // [8,4096]
    const float* W2 = (const float*)d_in[4];   // [8,1024,4096]
    const float* b2 = (const float*)d_in[5];   // [8,1024]
    float* out = (float*)d_out;

    void *p_xh, *p_w1h, *p_w2h, *p_hh, *p_y;
    cudaGetSymbolAddress(&p_xh, g_xh);
    cudaGetSymbolAddress(&p_w1h, g_W1h);
    cudaGetSymbolAddress(&p_w2h, g_W2h);
    cudaGetSymbolAddress(&p_hh, g_Hh);
    cudaGetSymbolAddress(&p_y, g_Y);

    cudaFuncSetAttribute(expert_gemm_mma3<H_DIM, D_DIM, true>,
                         cudaFuncAttributeMaxDynamicSharedMemorySize, SMEM_GEMM);
    cudaFuncSetAttribute(expert_gemm_mma3<D_DIM, H_DIM, false>,
                         cudaFuncAttributeMaxDynamicSharedMemorySize, SMEM_GEMM);

    router_kernel<<<T_TOK, 128>>>(x, Wg);
    finalize_kernel<<<1, 1024>>>(out, out_size);

    round_kernel<<<256, 256>>>((const float4*)x, (uint4*)p_xh,
                               (int)((size_t)T_TOK * D_DIM / 8));
    round_w_kernel<<<4096, 256>>>((const float4*)W1, (const float4*)W2,
                                  (uint4*)p_w1h, (uint4*)p_w2h);

    // fc1: x[gathered] @ W1^T -> relu -> Hh   (tile 128x128, ~1150 active CTAs)
    {
        dim3 grid(H_DIM / 128, T_TOK / 128, E_NUM);
        expert_gemm_mma3<H_DIM, D_DIM, true><<<grid, 256, SMEM_GEMM>>>(
            (const __half*)p_xh, (const __half*)p_w1h, b1, (__half*)p_hh, nullptr);
    }
    // fc2: H @ W2^T -> *prob -> Y   (tile 128x128, 256 CTAs, 2/SM)
    {
        dim3 grid(D_DIM / 128, T_TOK / 128, E_NUM);
        expert_gemm_mma3<D_DIM, H_DIM, false><<<grid, 256, SMEM_GEMM>>>(
            (const __half*)p_hh, (const __half*)p_w2h, b2, nullptr, (float*)p_y);
    }
    combine_kernel<<<T_TOK, 256>>>(out);
}

// round 16
// speedup vs baseline: 1.3508x; 1.3508x over previous
#include <cuda_runtime.h>
#include <cuda_fp16.h>
#include <math.h>
#include <stdint.h>

// Problem constants
#define T_TOK 2048        // B*S
#define D_DIM 1024
#define H_DIM 4096
#define E_NUM 8
#define TOPK 2
#define N_SLOTS (T_TOK * TOPK)    // 4096
#define OUT_ELEMS (T_TOK * D_DIM) // 2097152

// ---------------- device scratch (static, allocation-free) ----------------
__device__ int   g_counts[E_NUM];
__device__ int   g_offsets[E_NUM + 1];
__device__ int   g_cursor[E_NUM];
__device__ int   g_slot_tok[N_SLOTS];
__device__ float g_slot_prob[N_SLOTS];
__device__ int   g_tok_slot[T_TOK * TOPK];
__device__ int   g_top_e[T_TOK * TOPK];
__device__ float g_top_p[T_TOK * TOPK];
__device__ float g_probs8[T_TOK * E_NUM];

__device__ __align__(16) __half g_xh[(size_t)T_TOK * D_DIM];
__device__ __align__(16) __half g_W1h[(size_t)E_NUM * H_DIM * D_DIM];
__device__ __align__(16) __half g_W2h[(size_t)E_NUM * D_DIM * H_DIM];
__device__ __align__(16) __half g_Hh[(size_t)N_SLOTS * H_DIM];
__device__ __align__(16) float g_Y[(size_t)N_SLOTS * D_DIM];

// ---------------- PTX helpers (sm_80-class only; no 'a' features) ----------------
__device__ __forceinline__ uint32_t smem_u32(const void* p) {
    return (uint32_t)__cvta_generic_to_shared(p);
}

__device__ __forceinline__ void cp16(uint32_t saddr, const void* gaddr) {
    asm volatile("cp.async.cg.shared.global [%0], [%1], 16;" :: "r"(saddr), "l"(gaddr));
}
#define CP_COMMIT() asm volatile("cp.async.commit_group;" ::: "memory")
#define CP_WAIT_2() asm volatile("cp.async.wait_group 2;" ::: "memory")

__device__ __forceinline__ void ldsm_x4(uint32_t* r, uint32_t addr) {
    asm volatile("ldmatrix.sync.aligned.m8n8.x4.shared.b16 {%0,%1,%2,%3}, [%4];"
        : "=r"(r[0]), "=r"(r[1]), "=r"(r[2]), "=r"(r[3]) : "r"(addr));
}
__device__ __forceinline__ void ldsm_x2(uint32_t* r, uint32_t addr) {
    asm volatile("ldmatrix.sync.aligned.m8n8.x2.shared.b16 {%0,%1}, [%2];"
        : "=r"(r[0]), "=r"(r[1]) : "r"(addr));
}

__device__ __forceinline__ void mma16816(float* d, const uint32_t* a, const uint32_t* b) {
    asm volatile(
        "mma.sync.aligned.m16n8k16.row.col.f32.f16.f16.f32 "
        "{%0,%1,%2,%3}, {%4,%5,%6,%7}, {%8,%9}, {%0,%1,%2,%3};"
        : "+f"(d[0]), "+f"(d[1]), "+f"(d[2]), "+f"(d[3])
        : "r"(a[0]), "r"(a[1]), "r"(a[2]), "r"(a[3]), "r"(b[0]), "r"(b[1]));
}

// ---------------- init ----------------
__global__ void init_kernel() {
    if (threadIdx.x < E_NUM) g_counts[threadIdx.x] = 0;
}

// ---------------- router ----------------
__global__ void router_kernel(const float* __restrict__ x,
                              const float* __restrict__ Wg) {
    const int t = blockIdx.x;
    const float* xr = x + (size_t)t * D_DIM;
    float acc[E_NUM];
#pragma unroll
    for (int e = 0; e < E_NUM; e++) acc[e] = 0.f;

    for (int d = threadIdx.x; d < D_DIM; d += 128) {
        float xv = xr[d];
#pragma unroll
        for (int e = 0; e < E_NUM; e++)
            acc[e] = fmaf(xv, Wg[e * D_DIM + d], acc[e]);
    }
#pragma unroll
    for (int e = 0; e < E_NUM; e++)
#pragma unroll
        for (int off = 16; off > 0; off >>= 1)
            acc[e] += __shfl_xor_sync(0xffffffffu, acc[e], off);

    __shared__ float s[E_NUM][4];
    const int warp = threadIdx.x >> 5, lane = threadIdx.x & 31;
    if (lane == 0)
#pragma unroll
        for (int e = 0; e < E_NUM; e++) s[e][warp] = acc[e];
    __syncthreads();

    if (threadIdx.x == 0) {
        float lg[E_NUM];
#pragma unroll
        for (int e = 0; e < E_NUM; e++)
            lg[e] = s[e][0] + s[e][1] + s[e][2] + s[e][3];
        float mx = lg[0];
#pragma unroll
        for (int e = 1; e < E_NUM; e++) mx = fmaxf(mx, lg[e]);
        float se = 0.f, pe[E_NUM];
#pragma unroll
        for (int e = 0; e < E_NUM; e++) { pe[e] = expf(lg[e] - mx); se += pe[e]; }
        float inv = 1.f / se;
#pragma unroll
        for (int e = 0; e < E_NUM; e++) g_probs8[t * E_NUM + e] = pe[e] * inv;
        int i1 = 0;
#pragma unroll
        for (int e = 1; e < E_NUM; e++) if (lg[e] > lg[i1]) i1 = e;
        int i2 = -1;
#pragma unroll
        for (int e = 0; e < E_NUM; e++) {
            if (e == i1) continue;
            if (i2 < 0 || lg[e] > lg[i2]) i2 = e;
        }
        float v1 = lg[i1], v2 = lg[i2];
        float m = fmaxf(v1, v2);
        float e1 = expf(v1 - m), e2 = expf(v2 - m);
        float denom = 1.f / (e1 + e2);
        g_top_e[t * 2 + 0] = i1;  g_top_e[t * 2 + 1] = i2;
        g_top_p[t * 2 + 0] = e1 * denom;
        g_top_p[t * 2 + 1] = e2 * denom;
        atomicAdd(&g_counts[i1], 1);
        atomicAdd(&g_counts[i2], 1);
    }
}

// ---------------- finalize: offsets + scatter + aux (one CTA) ----------------
__global__ void finalize_kernel(float* __restrict__ out, int out_size) {
    const int tid = threadIdx.x;   // 1024 threads
    if (tid == 0) {
        int o = 0;
        for (int e = 0; e < E_NUM; e++) {
            g_offsets[e] = o; g_cursor[e] = o; o += g_counts[e];
        }
        g_offsets[E_NUM] = o;
    }
    __syncthreads();

    for (int t = tid; t < T_TOK; t += 1024) {
#pragma unroll
        for (int k = 0; k < TOPK; k++) {
            int e = g_top_e[t * 2 + k];
            int sidx = atomicAdd(&g_cursor[e], 1);
            g_slot_tok[sidx]  = t;
            g_slot_prob[sidx] = g_top_p[t * 2 + k];
            g_tok_slot[t * 2 + k] = sidx;
        }
    }

    __shared__ float red[E_NUM][1024];
    float ls[E_NUM];
#pragma unroll
    for (int e = 0; e < E_NUM; e++) ls[e] = 0.f;
    for (int t = tid; t < T_TOK; t += 1024)
#pragma unroll
        for (int e = 0; e < E_NUM; e++) ls[e] += g_probs8[t * E_NUM + e];
#pragma unroll
    for (int e = 0; e < E_NUM; e++) red[e][tid] = ls[e];
    __syncthreads();
    for (int st = 512; st > 0; st >>= 1) {
        if (tid < st)
#pragma unroll
            for (int e = 0; e < E_NUM; e++)
                red[e][tid] += red[e][tid + st];
        __syncthreads();
    }
    if (tid == 0 && out_size > OUT_ELEMS) {
        float aux = 0.f;
        for (int e = 0; e < E_NUM; e++)
            aux += (red[e][0] / (float)T_TOK) * ((float)g_counts[e] / (float)T_TOK);
        out[OUT_ELEMS] = (float)E_NUM * aux;
    }
}

// ---------------- fp32 -> fp16 round (wide: 8 floats -> 1 uint4 store) ------
__global__ void round_kernel(const float4* __restrict__ src,
                             uint4* __restrict__ dst, int n8) {
    int i = blockIdx.x * blockDim.x + threadIdx.x;
    int stride = gridDim.x * blockDim.x;
    for (; i < n8; i += stride) {
        float4 v0 = src[2 * i];
        float4 v1 = src[2 * i + 1];
        uint4 o;
        o.x = (uint32_t)__half_as_ushort(__float2half_rn(v0.x)) |
              ((uint32_t)__half_as_ushort(__float2half_rn(v0.y)) << 16);
        o.y = (uint32_t)__half_as_ushort(__float2half_rn(v0.z)) |
              ((uint32_t)__half_as_ushort(__float2half_rn(v0.w)) << 16);
        o.z = (uint32_t)__half_as_ushort(__float2half_rn(v1.x)) |
              ((uint32_t)__half_as_ushort(__float2half_rn(v1.y)) << 16);
        o.w = (uint32_t)__half_as_ushort(__float2half_rn(v1.z)) |
              ((uint32_t)__half_as_ushort(__float2half_rn(v1.w)) << 16);
        dst[i] = o;
    }
}

// ---------------- mma.sync grouped expert GEMM (256 threads, fp16) ----------
// Block tile 128x128, 8 warps in 2x4 grid, warp tile 64x32 (proven shape).
// __launch_bounds__(256, 2): 2 CTAs/SM co-resident -> 4 warps/SMSP chip-wide,
// fine CTA granularity for wave balance.
// K=32 per stage, 4 smem stages, prefetch depth 3, one sync/chunk.

#define KCHUNK 32
#define ROWPAD 40
#define ROWB   (ROWPAD * 2)            // 80 bytes per smem row
#define NSTAGE 4
#define BM 128
#define BN 128

template <int N_DIM, int K_DIM, bool FC1>
__global__ void __launch_bounds__(256, 2)
expert_gemm_mma3(const __half* __restrict__ A_g,
                 const __half* __restrict__ B_g,
                 const float* __restrict__ bias,
                 __half* __restrict__ H_out,
                 float* __restrict__ Y_out) {
    constexpr int NC = K_DIM / KCHUNK;
    constexpr int OFF_A = 0;
    constexpr int OFF_B = BM * ROWB;
    constexpr int ROWS_TOT = BM + BN;       // 256
    constexpr int STAGE_B = ROWS_TOT * ROWB;
    constexpr int NJ = 4;                   // 1024 chunks / 256 threads

    const int e = blockIdx.z;
    const int row_beg = g_offsets[e];
    const int row_end = g_offsets[e + 1];
    const int m0 = row_beg + blockIdx.y * BM;
    if (m0 >= row_end) return;
    const int n0 = blockIdx.x * BN;

    const __half* B_e = B_g + (size_t)e * N_DIM * K_DIM;
    const float* biasE = bias + e * N_DIM;

    extern __shared__ char smem[];
    const uint32_t smb = smem_u32(smem);
    const int tid = threadIdx.x;
    const int wid = tid >> 5;
    const int lane = tid & 31;
    const int warp_m = wid >> 2;   // 0..1  (64-row slice)
    const int warp_n = wid & 3;    // 0..3  (32-col slice)

    // ---- per-thread cp.async sources: 4 chunks (chunk id = tid + 256j) ----
    const __half* gsrc[NJ];
    uint32_t sOff[NJ];
#pragma unroll
    for (int j = 0; j < NJ; j++) {
        const int cidx = tid + 256 * j;     // 0..1023
        const int r = cidx >> 2;            // 0..255
        const int c16 = cidx & 3;
        const int kc8 = c16 * 8;
        if (r < BM) {
            int rowg = m0 + r;
            int clr = rowg < row_end ? rowg : (row_end - 1);
            int atok = FC1 ? g_slot_tok[clr] : clr;
            gsrc[j] = A_g + (size_t)atok * K_DIM + kc8;
            sOff[j] = (uint32_t)(OFF_A + r * ROWB + c16 * 16);
        } else {
            int rb = r - BM;
            gsrc[j] = B_e + (size_t)(n0 + rb) * K_DIM + kc8;
            sOff[j] = (uint32_t)(OFF_B + rb * ROWB + c16 * 16);
        }
    }

    // ---- ldmatrix per-thread base byte offsets ----
    const int l15 = lane & 15;
    const uint32_t aFrag = (uint32_t)(OFF_A + (warp_m * 64 + l15) * ROWB + (lane >> 4) * 16);
    const uint32_t bFrag = (uint32_t)(OFF_B + (warp_n * 32 + (l15 & 7)) * ROWB + ((l15 >> 3) & 1) * 16);

    float d[4][4][4];
#pragma unroll
    for (int mi = 0; mi < 4; mi++)
#pragma unroll
        for (int ni = 0; ni < 4; ni++)
#pragma unroll
            for (int q = 0; q < 4; q++) d[mi][ni][q] = 0.f;

#define ISSUE_STAGE(cidx2)                                                         \
    do {                                                                           \
        const uint32_t sb = smb + ((cidx2) % NSTAGE) * STAGE_B;                    \
        const int kk = (cidx2) * KCHUNK;                                           \
        _Pragma("unroll")                                                          \
        for (int j = 0; j < NJ; j++)                                               \
            cp16(sb + sOff[j], gsrc[j] + kk);                                      \
    } while (0)

    // prologue: 3 stages in flight
    ISSUE_STAGE(0); CP_COMMIT();
    ISSUE_STAGE(1); CP_COMMIT();
    ISSUE_STAGE(2); CP_COMMIT();

    for (int c = 0; c < NC; ++c) {
        CP_WAIT_2();       // stage c resident (uniform: one commit per iteration)
        __syncthreads();   // also guards reuse of buffer (c+3)%4 (read last iter)

        if (c + 3 < NC) ISSUE_STAGE(c + 3);
        CP_COMMIT();

        const uint32_t sb = smb + (c % NSTAGE) * STAGE_B;
        const uint32_t aB = sb + aFrag;
        const uint32_t bB = sb + bFrag;

#pragma unroll
        for (int ks = 0; ks < 2; ks++) {
            uint32_t Af[4][4], Bf[4][2];
#pragma unroll
            for (int mi = 0; mi < 4; mi++)
                ldsm_x4(Af[mi], aB + mi * (16 * ROWB) + ks * 32);
#pragma unroll
            for (int ni = 0; ni < 4; ni++)
                ldsm_x2(Bf[ni], bB + ni * (8 * ROWB) + ks * 32);
#pragma unroll
            for (int mi = 0; mi < 4; mi++)
#pragma unroll
                for (int ni = 0; ni < 4; ni++)
                    mma16816(d[mi][ni], Af[mi], Bf[ni]);
        }
    }

    // ---- epilogue ----
    const int rl = lane >> 2;          // 0..7
    const int cl = (lane & 3) * 2;     // 0,2,4,6
#pragma unroll
    for (int mi = 0; mi < 4; mi++) {
#pragma unroll
        for (int half = 0; half < 2; half++) {
            const int row = m0 + warp_m * 64 + mi * 16 + rl + half * 8;
            if (row >= row_end) continue;
            if (FC1) {
#pragma unroll
                for (int ni = 0; ni < 4; ni++) {
                    const int col = n0 + warp_n * 32 + ni * 8 + cl;
                    float v0 = fmaxf(d[mi][ni][half * 2 + 0] + biasE[col], 0.f);
                    float v1 = fmaxf(d[mi][ni][half * 2 + 1] + biasE[col + 1], 0.f);
                    __half h0 = __float2half_rn(v0), h1 = __float2half_rn(v1);
                    uint32_t hp = (uint32_t)__half_as_ushort(h0) |
                                  ((uint32_t)__half_as_ushort(h1) << 16);
                    *(uint32_t*)(H_out + (size_t)row * N_DIM + col) = hp;
                }
            } else {
                const float p = g_slot_prob[row];
#pragma unroll
                for (int ni = 0; ni < 4; ni++) {
                    const int col = n0 + warp_n * 32 + ni * 8 + cl;
                    float2 ov;
                    ov.x = (d[mi][ni][half * 2 + 0] + biasE[col])     * p;
                    ov.y = (d[mi][ni][half * 2 + 1] + biasE[col + 1]) * p;
                    *(float2*)(Y_out + (size_t)row * N_DIM + col) = ov;
                }
            }
        }
    }
#undef ISSUE_STAGE
}

#define SMEM_GEMM (NSTAGE * (BM + BN) * ROWB)   // 81920

// ---------------- combine ----------------
__global__ void combine_kernel(float* __restrict__ out) {
    const int t = blockIdx.x;
    const int s0 = g_tok_slot[t * 2 + 0];
    const int s1 = g_tok_slot[t * 2 + 1];
    const float4* y0 = (const float4*)(g_Y + (size_t)s0 * D_DIM);
    const float4* y1 = (const float4*)(g_Y + (size_t)s1 * D_DIM);
    float4* o = (float4*)(out + (size_t)t * D_DIM);
    int i = threadIdx.x;
    float4 a = y0[i], b = y1[i];
    o[i] = make_float4(a.x + b.x, a.y + b.y, a.z + b.z, a.w + b.w);
}

// ---------------- launch ----------------
extern "C" void kernel_launch(void* const* d_in, const int* in_sizes, int n_in,
                              void* d_out, int out_size) {
    const float* x  = (const float*)d_in[0];   // [2,1024,1024]
    const float* Wg = (const float*)d_in[1];   // [8,1024]
    const float* W1 = (const float*)d_in[2];   // [8,4096,1024]
    const float* b1 = (const float*)d_in[3];   // [8,4096]
    const float* W2 = (const float*)d_in[4];   // [8,1024,4096]
    const float* b2 = (const float*)d_in[5];   // [8,1024]
    float* out = (float*)d_out;

    void *p_xh, *p_w1h, *p_w2h, *p_hh, *p_y;
    cudaGetSymbolAddress(&p_xh, g_xh);
    cudaGetSymbolAddress(&p_w1h, g_W1h);
    cudaGetSymbolAddress(&p_w2h, g_W2h);
    cudaGetSymbolAddress(&p_hh, g_Hh);
    cudaGetSymbolAddress(&p_y, g_Y);

    cudaFuncSetAttribute(expert_gemm_mma3<H_DIM, D_DIM, true>,
                         cudaFuncAttributeMaxDynamicSharedMemorySize, SMEM_GEMM);
    cudaFuncSetAttribute(expert_gemm_mma3<D_DIM, H_DIM, false>,
                         cudaFuncAttributeMaxDynamicSharedMemorySize, SMEM_GEMM);

    init_kernel<<<1, 32>>>();
    router_kernel<<<T_TOK, 128>>>(x, Wg);
    finalize_kernel<<<1, 1024>>>(out, out_size);

    round_kernel<<<256, 256>>>((const float4*)x, (uint4*)p_xh,
                               (int)((size_t)T_TOK * D_DIM / 8));
    round_kernel<<<2048, 256>>>((const float4*)W1, (uint4*)p_w1h,
                                (int)((size_t)E_NUM * H_DIM * D_DIM / 8));
    round_kernel<<<2048, 256>>>((const float4*)W2, (uint4*)p_w2h,
                                (int)((size_t)E_NUM * D_DIM * H_DIM / 8));

    // fc1: x[gathered] @ W1^T -> relu -> Hh   (tile 128x128, ~1024 active CTAs)
    {
        dim3 grid(H_DIM / 128, T_TOK / 128, E_NUM);
        expert_gemm_mma3<H_DIM, D_DIM, true><<<grid, 256, SMEM_GEMM>>>(
            (const __half*)p_xh, (const __half*)p_w1h, b1, (__half*)p_hh, nullptr);
    }
    // fc2: H @ W2^T -> *prob -> Y   (tile 128x128, ~256 active CTAs, 2/SM)
    {
        dim3 grid(D_DIM / 128, T_TOK / 128, E_NUM);
        expert_gemm_mma3<D_DIM, H_DIM, false><<<grid, 256, SMEM_GEMM>>>(
            (const __half*)p_hh, (const __half*)p_w2h, b2, nullptr, (float*)p_y);
    }
    combine_kernel<<<T_TOK, 256>>>(out);
}

// round 17
// speedup vs baseline: 1.3739x; 1.0171x over previous
#include <cuda_runtime.h>
#include <cuda_fp16.h>
#include <math.h>
#include <stdint.h>

// Problem constants
#define T_TOK 2048        // B*S
#define D_DIM 1024
#define H_DIM 4096
#define E_NUM 8
#define TOPK 2
#define N_SLOTS (T_TOK * TOPK)    // 4096
#define OUT_ELEMS (T_TOK * D_DIM) // 2097152

// ---------------- device scratch (static, allocation-free) ----------------
__device__ int   g_counts[E_NUM];
__device__ int   g_offsets[E_NUM + 1];
__device__ int   g_cursor[E_NUM];
__device__ int   g_slot_tok[N_SLOTS];
__device__ float g_slot_prob[N_SLOTS];
__device__ int   g_tok_slot[T_TOK * TOPK];
__device__ int   g_top_e[T_TOK * TOPK];
__device__ float g_top_p[T_TOK * TOPK];
__device__ float g_probs8[T_TOK * E_NUM];

__device__ __align__(16) __half g_xh[(size_t)T_TOK * D_DIM];
__device__ __align__(16) __half g_W1h[(size_t)E_NUM * H_DIM * D_DIM];
__device__ __align__(16) __half g_W2h[(size_t)E_NUM * D_DIM * H_DIM];
__device__ __align__(16) __half g_Hh[(size_t)N_SLOTS * H_DIM];
__device__ __align__(16) float g_Y[(size_t)N_SLOTS * D_DIM];

// ---------------- PTX helpers (sm_80-class only; no 'a' features) ----------------
__device__ __forceinline__ uint32_t smem_u32(const void* p) {
    return (uint32_t)__cvta_generic_to_shared(p);
}

__device__ __forceinline__ void cp16(uint32_t saddr, const void* gaddr) {
    asm volatile("cp.async.cg.shared.global [%0], [%1], 16;" :: "r"(saddr), "l"(gaddr));
}
#define CP_COMMIT() asm volatile("cp.async.commit_group;" ::: "memory")
#define CP_WAIT_2() asm volatile("cp.async.wait_group 2;" ::: "memory")

__device__ __forceinline__ void ldsm_x4(uint32_t* r, uint32_t addr) {
    asm volatile("ldmatrix.sync.aligned.m8n8.x4.shared.b16 {%0,%1,%2,%3}, [%4];"
        : "=r"(r[0]), "=r"(r[1]), "=r"(r[2]), "=r"(r[3]) : "r"(addr));
}
__device__ __forceinline__ void ldsm_x2(uint32_t* r, uint32_t addr) {
    asm volatile("ldmatrix.sync.aligned.m8n8.x2.shared.b16 {%0,%1}, [%2];"
        : "=r"(r[0]), "=r"(r[1]) : "r"(addr));
}

__device__ __forceinline__ void mma16816(float* d, const uint32_t* a, const uint32_t* b) {
    asm volatile(
        "mma.sync.aligned.m16n8k16.row.col.f32.f16.f16.f32 "
        "{%0,%1,%2,%3}, {%4,%5,%6,%7}, {%8,%9}, {%0,%1,%2,%3};"
        : "+f"(d[0]), "+f"(d[1]), "+f"(d[2]), "+f"(d[3])
        : "r"(a[0]), "r"(a[1]), "r"(a[2]), "r"(a[3]), "r"(b[0]), "r"(b[1]));
}

// ---------------- init ----------------
__global__ void init_kernel() {
    if (threadIdx.x < E_NUM) g_counts[threadIdx.x] = 0;
}

// ---------------- router ----------------
__global__ void router_kernel(const float* __restrict__ x,
                              const float* __restrict__ Wg) {
    const int t = blockIdx.x;
    const float* xr = x + (size_t)t * D_DIM;
    float acc[E_NUM];
#pragma unroll
    for (int e = 0; e < E_NUM; e++) acc[e] = 0.f;

    for (int d = threadIdx.x; d < D_DIM; d += 128) {
        float xv = xr[d];
#pragma unroll
        for (int e = 0; e < E_NUM; e++)
            acc[e] = fmaf(xv, Wg[e * D_DIM + d], acc[e]);
    }
#pragma unroll
    for (int e = 0; e < E_NUM; e++)
#pragma unroll
        for (int off = 16; off > 0; off >>= 1)
            acc[e] += __shfl_xor_sync(0xffffffffu, acc[e], off);

    __shared__ float s[E_NUM][4];
    const int warp = threadIdx.x >> 5, lane = threadIdx.x & 31;
    if (lane == 0)
#pragma unroll
        for (int e = 0; e < E_NUM; e++) s[e][warp] = acc[e];
    __syncthreads();

    if (threadIdx.x == 0) {
        float lg[E_NUM];
#pragma unroll
        for (int e = 0; e < E_NUM; e++)
            lg[e] = s[e][0] + s[e][1] + s[e][2] + s[e][3];
        float mx = lg[0];
#pragma unroll
        for (int e = 1; e < E_NUM; e++) mx = fmaxf(mx, lg[e]);
        float se = 0.f, pe[E_NUM];
#pragma unroll
        for (int e = 0; e < E_NUM; e++) { pe[e] = expf(lg[e] - mx); se += pe[e]; }
        float inv = 1.f / se;
#pragma unroll
        for (int e = 0; e < E_NUM; e++) g_probs8[t * E_NUM + e] = pe[e] * inv;
        int i1 = 0;
#pragma unroll
        for (int e = 1; e < E_NUM; e++) if (lg[e] > lg[i1]) i1 = e;
        int i2 = -1;
#pragma unroll
        for (int e = 0; e < E_NUM; e++) {
            if (e == i1) continue;
            if (i2 < 0 || lg[e] > lg[i2]) i2 = e;
        }
        float v1 = lg[i1], v2 = lg[i2];
        float m = fmaxf(v1, v2);
        float e1 = expf(v1 - m), e2 = expf(v2 - m);
        float denom = 1.f / (e1 + e2);
        g_top_e[t * 2 + 0] = i1;  g_top_e[t * 2 + 1] = i2;
        g_top_p[t * 2 + 0] = e1 * denom;
        g_top_p[t * 2 + 1] = e2 * denom;
        atomicAdd(&g_counts[i1], 1);
        atomicAdd(&g_counts[i2], 1);
    }
}

// ---------------- finalize: offsets + scatter + aux (one CTA) ----------------
__global__ void finalize_kernel(float* __restrict__ out, int out_size) {
    const int tid = threadIdx.x;   // 1024 threads
    if (tid == 0) {
        int o = 0;
        for (int e = 0; e < E_NUM; e++) {
            g_offsets[e] = o; g_cursor[e] = o; o += g_counts[e];
        }
        g_offsets[E_NUM] = o;
    }
    __syncthreads();

    for (int t = tid; t < T_TOK; t += 1024) {
#pragma unroll
        for (int k = 0; k < TOPK; k++) {
            int e = g_top_e[t * 2 + k];
            int sidx = atomicAdd(&g_cursor[e], 1);
            g_slot_tok[sidx]  = t;
            g_slot_prob[sidx] = g_top_p[t * 2 + k];
            g_tok_slot[t * 2 + k] = sidx;
        }
    }

    __shared__ float red[E_NUM][1024];
    float ls[E_NUM];
#pragma unroll
    for (int e = 0; e < E_NUM; e++) ls[e] = 0.f;
    for (int t = tid; t < T_TOK; t += 1024)
#pragma unroll
        for (int e = 0; e < E_NUM; e++) ls[e] += g_probs8[t * E_NUM + e];
#pragma unroll
    for (int e = 0; e < E_NUM; e++) red[e][tid] = ls[e];
    __syncthreads();
    for (int st = 512; st > 0; st >>= 1) {
        if (tid < st)
#pragma unroll
            for (int e = 0; e < E_NUM; e++)
                red[e][tid] += red[e][tid + st];
        __syncthreads();
    }
    if (tid == 0 && out_size > OUT_ELEMS) {
        float aux = 0.f;
        for (int e = 0; e < E_NUM; e++)
            aux += (red[e][0] / (float)T_TOK) * ((float)g_counts[e] / (float)T_TOK);
        out[OUT_ELEMS] = (float)E_NUM * aux;
    }
}

// ---------------- fp32 -> fp16 round (wide: 8 floats -> 1 uint4 store) ------
__global__ void round_kernel(const float4* __restrict__ src,
                             uint4* __restrict__ dst, int n8) {
    int i = blockIdx.x * blockDim.x + threadIdx.x;
    int stride = gridDim.x * blockDim.x;
    for (; i < n8; i += stride) {
        float4 v0 = src[2 * i];
        float4 v1 = src[2 * i + 1];
        uint4 o;
        o.x = (uint32_t)__half_as_ushort(__float2half_rn(v0.x)) |
              ((uint32_t)__half_as_ushort(__float2half_rn(v0.y)) << 16);
        o.y = (uint32_t)__half_as_ushort(__float2half_rn(v0.z)) |
              ((uint32_t)__half_as_ushort(__float2half_rn(v0.w)) << 16);
        o.z = (uint32_t)__half_as_ushort(__float2half_rn(v1.x)) |
              ((uint32_t)__half_as_ushort(__float2half_rn(v1.y)) << 16);
        o.w = (uint32_t)__half_as_ushort(__float2half_rn(v1.z)) |
              ((uint32_t)__half_as_ushort(__float2half_rn(v1.w)) << 16);
        dst[i] = o;
    }
}

// ---------------- mma.sync grouped expert GEMM (256 threads, fp16) ----------
// EXACT round-12 configuration (best measured): block tile 128x128, 8 warps
// in 2x4 grid, warp tile 64x32, __launch_bounds__(256, 2) -> 2 CTAs/SM,
// K=32 per stage, 4 smem stages (80 KB), prefetch depth 3, one sync/chunk.

#define KCHUNK 32
#define ROWPAD 40
#define ROWB   (ROWPAD * 2)            // 80 bytes per smem row
#define NSTAGE 4
#define BM 128
#define BN 128

template <int N_DIM, int K_DIM, bool FC1>
__global__ void __launch_bounds__(256, 2)
expert_gemm_mma3(const __half* __restrict__ A_g,
                 const __half* __restrict__ B_g,
                 const float* __restrict__ bias,
                 __half* __restrict__ H_out,
                 float* __restrict__ Y_out) {
    constexpr int NC = K_DIM / KCHUNK;
    constexpr int OFF_A = 0;
    constexpr int OFF_B = BM * ROWB;
    constexpr int ROWS_TOT = BM + BN;       // 256
    constexpr int STAGE_B = ROWS_TOT * ROWB;
    constexpr int NJ = 4;                   // 1024 chunks / 256 threads

    const int e = blockIdx.z;
    const int row_beg = g_offsets[e];
    const int row_end = g_offsets[e + 1];
    const int m0 = row_beg + blockIdx.y * BM;
    if (m0 >= row_end) return;
    const int n0 = blockIdx.x * BN;

    const __half* B_e = B_g + (size_t)e * N_DIM * K_DIM;
    const float* biasE = bias + e * N_DIM;

    extern __shared__ char smem[];
    const uint32_t smb = smem_u32(smem);
    const int tid = threadIdx.x;
    const int wid = tid >> 5;
    const int lane = tid & 31;
    const int warp_m = wid >> 2;   // 0..1  (64-row slice)
    const int warp_n = wid & 3;    // 0..3  (32-col slice)

    // ---- per-thread cp.async sources: 4 chunks (chunk id = tid + 256j) ----
    const __half* gsrc[NJ];
    uint32_t sOff[NJ];
#pragma unroll
    for (int j = 0; j < NJ; j++) {
        const int cidx = tid + 256 * j;     // 0..1023
        const int r = cidx >> 2;            // 0..255
        const int c16 = cidx & 3;
        const int kc8 = c16 * 8;
        if (r < BM) {
            int rowg = m0 + r;
            int clr = rowg < row_end ? rowg : (row_end - 1);
            int atok = FC1 ? g_slot_tok[clr] : clr;
            gsrc[j] = A_g + (size_t)atok * K_DIM + kc8;
            sOff[j] = (uint32_t)(OFF_A + r * ROWB + c16 * 16);
        } else {
            int rb = r - BM;
            gsrc[j] = B_e + (size_t)(n0 + rb) * K_DIM + kc8;
            sOff[j] = (uint32_t)(OFF_B + rb * ROWB + c16 * 16);
        }
    }

    // ---- ldmatrix per-thread base byte offsets ----
    const int l15 = lane & 15;
    const uint32_t aFrag = (uint32_t)(OFF_A + (warp_m * 64 + l15) * ROWB + (lane >> 4) * 16);
    const uint32_t bFrag = (uint32_t)(OFF_B + (warp_n * 32 + (l15 & 7)) * ROWB + ((l15 >> 3) & 1) * 16);

    float d[4][4][4];
#pragma unroll
    for (int mi = 0; mi < 4; mi++)
#pragma unroll
        for (int ni = 0; ni < 4; ni++)
#pragma unroll
            for (int q = 0; q < 4; q++) d[mi][ni][q] = 0.f;

#define ISSUE_STAGE(cidx2)                                                         \
    do {                                                                           \
        const uint32_t sb = smb + ((cidx2) % NSTAGE) * STAGE_B;                    \
        const int kk = (cidx2) * KCHUNK;                                           \
        _Pragma("unroll")                                                          \
        for (int j = 0; j < NJ; j++)                                               \
            cp16(sb + sOff[j], gsrc[j] + kk);                                      \
    } while (0)

    // prologue: 3 stages in flight
    ISSUE_STAGE(0); CP_COMMIT();
    ISSUE_STAGE(1); CP_COMMIT();
    ISSUE_STAGE(2); CP_COMMIT();

    for (int c = 0; c < NC; ++c) {
        CP_WAIT_2();       // stage c resident (uniform: one commit per iteration)
        __syncthreads();   // also guards reuse of buffer (c+3)%4 (read last iter)

        if (c + 3 < NC) ISSUE_STAGE(c + 3);
        CP_COMMIT();

        const uint32_t sb = smb + (c % NSTAGE) * STAGE_B;
        const uint32_t aB = sb + aFrag;
        const uint32_t bB = sb + bFrag;

#pragma unroll
        for (int ks = 0; ks < 2; ks++) {
            uint32_t Af[4][4], Bf[4][2];
#pragma unroll
            for (int mi = 0; mi < 4; mi++)
                ldsm_x4(Af[mi], aB + mi * (16 * ROWB) + ks * 32);
#pragma unroll
            for (int ni = 0; ni < 4; ni++)
                ldsm_x2(Bf[ni], bB + ni * (8 * ROWB) + ks * 32);
#pragma unroll
            for (int mi = 0; mi < 4; mi++)
#pragma unroll
                for (int ni = 0; ni < 4; ni++)
                    mma16816(d[mi][ni], Af[mi], Bf[ni]);
        }
    }

    // ---- epilogue ----
    const int rl = lane >> 2;          // 0..7
    const int cl = (lane & 3) * 2;     // 0,2,4,6
#pragma unroll
    for (int mi = 0; mi < 4; mi++) {
#pragma unroll
        for (int half = 0; half < 2; half++) {
            const int row = m0 + warp_m * 64 + mi * 16 + rl + half * 8;
            if (row >= row_end) continue;
            if (FC1) {
#pragma unroll
                for (int ni = 0; ni < 4; ni++) {
                    const int col = n0 + warp_n * 32 + ni * 8 + cl;
                    float v0 = fmaxf(d[mi][ni][half * 2 + 0] + biasE[col], 0.f);
                    float v1 = fmaxf(d[mi][ni][half * 2 + 1] + biasE[col + 1], 0.f);
                    __half h0 = __float2half_rn(v0), h1 = __float2half_rn(v1);
                    uint32_t hp = (uint32_t)__half_as_ushort(h0) |
                                  ((uint32_t)__half_as_ushort(h1) << 16);
                    *(uint32_t*)(H_out + (size_t)row * N_DIM + col) = hp;
                }
            } else {
                const float p = g_slot_prob[row];
#pragma unroll
                for (int ni = 0; ni < 4; ni++) {
                    const int col = n0 + warp_n * 32 + ni * 8 + cl;
                    float2 ov;
                    ov.x = (d[mi][ni][half * 2 + 0] + biasE[col])     * p;
                    ov.y = (d[mi][ni][half * 2 + 1] + biasE[col + 1]) * p;
                    *(float2*)(Y_out + (size_t)row * N_DIM + col) = ov;
                }
            }
        }
    }
#undef ISSUE_STAGE
}

#define SMEM_GEMM (NSTAGE * (BM + BN) * ROWB)   // 81920

// ---------------- combine ----------------
__global__ void combine_kernel(float* __restrict__ out) {
    const int t = blockIdx.x;
    const int s0 = g_tok_slot[t * 2 + 0];
    const int s1 = g_tok_slot[t * 2 + 1];
    const float4* y0 = (const float4*)(g_Y + (size_t)s0 * D_DIM);
    const float4* y1 = (const float4*)(g_Y + (size_t)s1 * D_DIM);
    float4* o = (float4*)(out + (size_t)t * D_DIM);
    int i = threadIdx.x;
    float4 a = y0[i], b = y1[i];
    o[i] = make_float4(a.x + b.x, a.y + b.y, a.z + b.z, a.w + b.w);
}

// ---------------- launch ----------------
extern "C" void kernel_launch(void* const* d_in, const int* in_sizes, int n_in,
                              void* d_out, int out_size) {
    const float* x  = (const float*)d_in[0];   // [2,1024,1024]
    const float* Wg = (const float*)d_in[1];   // [8,1024]
    const float* W1 = (const float*)d_in[2];   // [8,4096,1024]
    const float* b1 = (const float*)d_in[3];   // [8,4096]
    const float* W2 = (const float*)d_in[4];   // [8,1024,4096]
    const float* b2 = (const float*)d_in[5];   // [8,1024]
    float* out = (float*)d_out;

    void *p_xh, *p_w1h, *p_w2h, *p_hh, *p_y;
    cudaGetSymbolAddress(&p_xh, g_xh);
    cudaGetSymbolAddress(&p_w1h, g_W1h);
    cudaGetSymbolAddress(&p_w2h, g_W2h);
    cudaGetSymbolAddress(&p_hh, g_Hh);
    cudaGetSymbolAddress(&p_y, g_Y);

    cudaFuncSetAttribute(expert_gemm_mma3<H_DIM, D_DIM, true>,
                         cudaFuncAttributeMaxDynamicSharedMemorySize, SMEM_GEMM);
    cudaFuncSetAttribute(expert_gemm_mma3<D_DIM, H_DIM, false>,
                         cudaFuncAttributeMaxDynamicSharedMemorySize, SMEM_GEMM);

    // lazy-created side stream + fork/join events (created on the first,
    // non-captured correctness call; only USED during capture — same GPU work
    // every call)
    static cudaStream_t s1 = nullptr;
    static cudaEvent_t evRoot = nullptr, evW1 = nullptr, evW2 = nullptr;
    if (s1 == nullptr) {
        cudaStreamCreateWithFlags(&s1, cudaStreamNonBlocking);
        cudaEventCreateWithFlags(&evRoot, cudaEventDisableTiming);
        cudaEventCreateWithFlags(&evW1, cudaEventDisableTiming);
        cudaEventCreateWithFlags(&evW2, cudaEventDisableTiming);
    }

    // fork: side stream does the big weight rounds
    cudaEventRecord(evRoot, 0);
    cudaStreamWaitEvent(s1, evRoot, 0);
    round_kernel<<<2048, 256, 0, s1>>>((const float4*)W1, (uint4*)p_w1h,
                                       (int)((size_t)E_NUM * H_DIM * D_DIM / 8));
    cudaEventRecord(evW1, s1);
    round_kernel<<<2048, 256, 0, s1>>>((const float4*)W2, (uint4*)p_w2h,
                                       (int)((size_t)E_NUM * D_DIM * H_DIM / 8));
    cudaEventRecord(evW2, s1);

    // main stream: routing + x round (overlaps W1 round)
    init_kernel<<<1, 32>>>();
    router_kernel<<<T_TOK, 128>>>(x, Wg);
    finalize_kernel<<<1, 1024>>>(out, out_size);
    round_kernel<<<256, 256>>>((const float4*)x, (uint4*)p_xh,
                               (int)((size_t)T_TOK * D_DIM / 8));

    // fc1 needs W1h; W2 round overlaps fc1
    cudaStreamWaitEvent(0, evW1, 0);
    {
        dim3 grid(H_DIM / 128, T_TOK / 128, E_NUM);
        expert_gemm_mma3<H_DIM, D_DIM, true><<<grid, 256, SMEM_GEMM>>>(
            (const __half*)p_xh, (const __half*)p_w1h, b1, (__half*)p_hh, nullptr);
    }
    // fc2 needs W2h (join side stream)
    cudaStreamWaitEvent(0, evW2, 0);
    {
        dim3 grid(D_DIM / 128, T_TOK / 128, E_NUM);
        expert_gemm_mma3<D_DIM, H_DIM, false><<<grid, 256, SMEM_GEMM>>>(
            (const __half*)p_hh, (const __half*)p_w2h, b2, nullptr, (float*)p_y);
    }
    combine_kernel<<<T_TOK, 256>>>(out);
}